// round 4
// baseline (speedup 1.0000x reference)
#include <cuda_runtime.h>

#define N_ROWS 64
#define SD 65536
#define PI_F 3.14159265358979323846f
#define RS2 0.70710678118654752440f

// ---------------- device scratch (no allocations allowed) ----------------
static __device__ float  g_sr[N_ROWS * SD];   // 16 MB state real
static __device__ float  g_si[N_ROWS * SD];   // 16 MB state imag
static __device__ float  g_Pl[N_ROWS][256];   // product-state factor, qubits 0..7
static __device__ float  g_Ph[N_ROWS][256];   // product-state factor, qubits 8..15
static __device__ float2 g_A1[512];           // D1 phase, qubits 0..7   (bits 0..8)
static __device__ float2 g_B1[512];           // D1 phase, qubits 8..15  (bits 8..15, bit0)
static __device__ float2 g_C2[1024];          // D2 phase, qubits 0..7   (bits 0..9)
static __device__ float2 g_E2[1024];          // D2 phase, qubits 8..15  (bits 8..15, bits0..1)
static __device__ float  g_cm[N_ROWS][16];    // cos of merged mid RY angle /2
static __device__ float  g_sm[N_ROWS][16];
static __device__ float  g_ce[16];            // cos of end RY angle /2 (row independent)
static __device__ float  g_se[16];
static __device__ float  g_z[N_ROWS][16];     // Z expectation accumulators

// smem bank swizzle (consistent everywhere -> correctness independent of analysis)
#define SW(l) ((l) ^ (((l) >> 5) & 31))

__device__ __forceinline__ float2 cmul(float2 a, float2 b) {
    return make_float2(a.x * b.x - a.y * b.y, a.x * b.y + a.y * b.x);
}

__device__ __forceinline__ void rot2(float& a, float& b, float c, float s) {
    float t0 = a, t1 = b;
    a = c * t0 - s * t1;
    b = s * t0 + c * t1;
}
// RY gate on bit-k of the 3-bit register block (8 amplitudes per thread)
__device__ __forceinline__ void gbit0(float vr[8], float vi[8], float c, float s) {
    rot2(vr[0], vr[1], c, s); rot2(vr[2], vr[3], c, s); rot2(vr[4], vr[5], c, s); rot2(vr[6], vr[7], c, s);
    rot2(vi[0], vi[1], c, s); rot2(vi[2], vi[3], c, s); rot2(vi[4], vi[5], c, s); rot2(vi[6], vi[7], c, s);
}
__device__ __forceinline__ void gbit1(float vr[8], float vi[8], float c, float s) {
    rot2(vr[0], vr[2], c, s); rot2(vr[1], vr[3], c, s); rot2(vr[4], vr[6], c, s); rot2(vr[5], vr[7], c, s);
    rot2(vi[0], vi[2], c, s); rot2(vi[1], vi[3], c, s); rot2(vi[4], vi[6], c, s); rot2(vi[5], vi[7], c, s);
}
__device__ __forceinline__ void gbit2(float vr[8], float vi[8], float c, float s) {
    rot2(vr[0], vr[4], c, s); rot2(vr[1], vr[5], c, s); rot2(vr[2], vr[6], c, s); rot2(vr[3], vr[7], c, s);
    rot2(vi[0], vi[4], c, s); rot2(vi[1], vi[5], c, s); rot2(vi[2], vi[6], c, s); rot2(vi[3], vi[7], c, s);
}

// ---------------- K0: build all tables + zero accumulators ----------------
__global__ void qk0(const float* __restrict__ x, const float* __restrict__ wcrz,
                    const float* __restrict__ wry, const float* __restrict__ scal) {
    __shared__ float u0[16], u1[16];
    __shared__ float cc[2][16], ss[2][16];
    int blk = blockIdx.x, tid = threadIdx.x;
    if (blk < N_ROWS) {
        int r = blk;
        if (tid < 16) {
            int q = tid, h = q >> 2, w = q & 3, b = r >> 3, p = r & 7;
            float e = tanhf(x[b * 128 + h * 32 + p * 4 + w] * scal[0]) * PI_F;
            float c, s; sincosf(0.5f * e, &s, &c);
            u0[q] = (c - s) * RS2;      // amplitude on |0> after RY(e)·H|0>
            u1[q] = (c + s) * RS2;      // amplitude on |1>
            float mth = wry[q] + e;     // merged RY: layer0 w_ry + layer1 re-encode
            float cm, sm; sincosf(0.5f * mth, &sm, &cm);
            g_cm[r][q] = cm; g_sm[r][q] = sm;
            g_z[r][q] = 0.f;            // reset accumulators every launch (graph replay safe)
        }
        __syncthreads();
        for (int m2 = tid; m2 < 256; m2 += blockDim.x) {
            float pl = 1.f, ph = 1.f;
#pragma unroll
            for (int q = 0; q < 8; q++) {
                pl *= ((m2 >> q) & 1) ? u1[q] : u0[q];
                ph *= ((m2 >> q) & 1) ? u1[8 + q] : u0[8 + q];
            }
            g_Pl[r][m2] = pl; g_Ph[r][m2] = ph;
        }
    } else {
        // global (row-independent) tables
        if (tid < 32) {
            int L = tid >> 4, q = tid & 15;
            float c, s; sincosf(0.5f * wcrz[L * 16 + q], &s, &c);
            cc[L][q] = c; ss[L][q] = s;
        }
        if (tid < 16) {
            float c, s; sincosf(0.5f * wry[16 + tid], &s, &c);
            g_ce[tid] = c; g_se[tid] = s;
        }
        __syncthreads();
        // D1 tables (shift 1): A1 over bits 0..8, B1 over bits 8..15 + bit0
        for (int idx = tid; idx < 512; idx += blockDim.x) {
            float2 a = make_float2(1.f, 0.f);
#pragma unroll
            for (int q = 0; q < 8; q++) {
                if ((idx >> q) & 1) {
                    float t = ((idx >> (q + 1)) & 1) ? ss[0][q] : -ss[0][q];
                    a = cmul(a, make_float2(cc[0][q], t));
                }
            }
            g_A1[idx] = a;
            float2 bp = make_float2(1.f, 0.f);
#pragma unroll
            for (int q = 8; q < 16; q++) {
                if ((idx >> (q - 8)) & 1) {
                    int bt = (q < 15) ? ((idx >> (q - 7)) & 1) : ((idx >> 8) & 1);
                    float t = bt ? ss[0][q] : -ss[0][q];
                    bp = cmul(bp, make_float2(cc[0][q], t));
                }
            }
            g_B1[idx] = bp;
        }
        // D2 tables (shift 2): C2 over bits 0..9, E2 over bits 8..15 + bits 0..1
        for (int idx = tid; idx < 1024; idx += blockDim.x) {
            float2 a = make_float2(1.f, 0.f);
#pragma unroll
            for (int q = 0; q < 8; q++) {
                if ((idx >> q) & 1) {
                    float t = ((idx >> (q + 2)) & 1) ? ss[1][q] : -ss[1][q];
                    a = cmul(a, make_float2(cc[1][q], t));
                }
            }
            g_C2[idx] = a;
            float2 e = make_float2(1.f, 0.f);
#pragma unroll
            for (int q = 8; q < 16; q++) {
                if ((idx >> (q - 8)) & 1) {
                    int bt = (q < 14) ? ((idx >> (q - 6)) & 1)
                                      : ((q == 14) ? ((idx >> 8) & 1) : ((idx >> 9) & 1));
                    float t = bt ? ss[1][q] : -ss[1][q];
                    e = cmul(e, make_float2(cc[1][q], t));
                }
            }
            g_E2[idx] = e;
        }
    }
}

// ---------------- K1: init (P·D1) + mid RY on qubits 0..11 ----------------
// chunk = contiguous low-12 bits; CTA = (row, hi bits 12..15)
__global__ __launch_bounds__(512) void qk1() {
    __shared__ float sr[4096], si[4096];
    __shared__ float mc[12], ms[12];
    int blk = blockIdx.x, t = threadIdx.x;
    int r = blk >> 4, hi = blk & 15;
    if (t < 12) { mc[t] = g_cm[r][t]; ms[t] = g_sm[r][t]; }
    __syncthreads();
    float vr[8], vi[8];
    {   // init + gates q0,1,2 (bits 0..2 in registers)
#pragma unroll
        for (int j = 0; j < 8; j++) {
            int l = (t << 3) | j; int b = (hi << 12) | l;
            float p = g_Pl[r][b & 255] * g_Ph[r][(b >> 8) & 255];
            float2 a = g_A1[b & 511];
            float2 bb = g_B1[(b >> 8) | ((b & 1) << 8)];
            vr[j] = p * (a.x * bb.x - a.y * bb.y);
            vi[j] = p * (a.x * bb.y + a.y * bb.x);
        }
        gbit0(vr, vi, mc[0], ms[0]); gbit1(vr, vi, mc[1], ms[1]); gbit2(vr, vi, mc[2], ms[2]);
#pragma unroll
        for (int j = 0; j < 8; j++) { int l = (t << 3) | j; sr[SW(l)] = vr[j]; si[SW(l)] = vi[j]; }
    }
    __syncthreads();
    {   // gates q3,4,5
        int l0 = (t & 7) | (((t >> 5) & 3) << 6) | (((t >> 3) & 3) << 8) | (((t >> 7) & 3) << 10);
#pragma unroll
        for (int j = 0; j < 8; j++) { int l = l0 | (j << 3); vr[j] = sr[SW(l)]; vi[j] = si[SW(l)]; }
        gbit0(vr, vi, mc[3], ms[3]); gbit1(vr, vi, mc[4], ms[4]); gbit2(vr, vi, mc[5], ms[5]);
#pragma unroll
        for (int j = 0; j < 8; j++) { int l = l0 | (j << 3); sr[SW(l)] = vr[j]; si[SW(l)] = vi[j]; }
    }
    __syncthreads();
    {   // gates q6,7,8
        int l0 = (t & 63) | ((t >> 6) << 9);
#pragma unroll
        for (int j = 0; j < 8; j++) { int l = l0 | (j << 6); vr[j] = sr[SW(l)]; vi[j] = si[SW(l)]; }
        gbit0(vr, vi, mc[6], ms[6]); gbit1(vr, vi, mc[7], ms[7]); gbit2(vr, vi, mc[8], ms[8]);
#pragma unroll
        for (int j = 0; j < 8; j++) { int l = l0 | (j << 6); sr[SW(l)] = vr[j]; si[SW(l)] = vi[j]; }
    }
    __syncthreads();
    {   // gates q9,10,11 + coalesced global store
#pragma unroll
        for (int j = 0; j < 8; j++) { int l = t | (j << 9); vr[j] = sr[SW(l)]; vi[j] = si[SW(l)]; }
        gbit0(vr, vi, mc[9], ms[9]); gbit1(vr, vi, mc[10], ms[10]); gbit2(vr, vi, mc[11], ms[11]);
        float* gr = g_sr + (r << 16) + (hi << 12);
        float* gi = g_si + (r << 16) + (hi << 12);
#pragma unroll
        for (int j = 0; j < 8; j++) { int l = t | (j << 9); gr[l] = vr[j]; gi[l] = vi[j]; }
    }
}

// ---------------- K2: mid RY 12..15, D2, end RY 0..7 & 12..15 ----------------
// chunk: local bits 0..7 = global bits 0..7, local bits 8..11 = global bits 12..15
// CTA = (row, m = global bits 8..11)
__global__ __launch_bounds__(512) void qk2() {
    __shared__ float sr[4096], si[4096];
    __shared__ float mc4[4], ms4[4], ce[16], se[16];
    int blk = blockIdx.x, t = threadIdx.x;
    int r = blk >> 4, m = blk & 15;
    if (t < 4) { mc4[t] = g_cm[r][12 + t]; ms4[t] = g_sm[r][12 + t]; }
    if (t >= 32 && t < 48) { ce[t - 32] = g_ce[t - 32]; se[t - 32] = g_se[t - 32]; }
    __syncthreads();
    float vr[8], vi[8];
    const float* gr = g_sr + (r << 16);
    const float* gi = g_si + (r << 16);
    {   // global load + mid gates on global q12,13,14 (local bits 8,9,10)
        int l0 = (t & 255) | (((t >> 8) & 1) << 11);
#pragma unroll
        for (int j = 0; j < 8; j++) {
            int l = l0 | (j << 8);
            int b = (l & 255) | (m << 8) | ((l >> 8) << 12);
            vr[j] = gr[b]; vi[j] = gi[b];
        }
        gbit0(vr, vi, mc4[0], ms4[0]); gbit1(vr, vi, mc4[1], ms4[1]); gbit2(vr, vi, mc4[2], ms4[2]);
#pragma unroll
        for (int j = 0; j < 8; j++) { int l = l0 | (j << 8); sr[SW(l)] = vr[j]; si[SW(l)] = vi[j]; }
    }
    __syncthreads();
    {   // mid q15 (local bit 11) -> D2 phase -> end q0, q1, q15
        int l0 = (t & 511) << 2;
#pragma unroll
        for (int j = 0; j < 8; j++) {
            int l = l0 | (j & 3) | ((j >> 2) << 11);
            vr[j] = sr[SW(l)]; vi[j] = si[SW(l)];
        }
        gbit2(vr, vi, mc4[3], ms4[3]);   // mid RY on global q15
#pragma unroll
        for (int j = 0; j < 8; j++) {    // D2 diagonal phase
            int l = l0 | (j & 3) | ((j >> 2) << 11);
            int b = (l & 255) | (m << 8) | ((l >> 8) << 12);
            float2 c2 = g_C2[b & 1023];
            float2 e2 = g_E2[(b >> 8) | ((b & 3) << 8)];
            float phr = c2.x * e2.x - c2.y * e2.y;
            float phi = c2.x * e2.y + c2.y * e2.x;
            float nr = vr[j] * phr - vi[j] * phi;
            vi[j] = vr[j] * phi + vi[j] * phr;
            vr[j] = nr;
        }
        gbit0(vr, vi, ce[0], se[0]); gbit1(vr, vi, ce[1], se[1]); gbit2(vr, vi, ce[15], se[15]);
#pragma unroll
        for (int j = 0; j < 8; j++) {
            int l = l0 | (j & 3) | ((j >> 2) << 11);
            sr[SW(l)] = vr[j]; si[SW(l)] = vi[j];
        }
    }
    __syncthreads();
    {   // end q2,3,4
        int l0 = (t & 3) | (((t >> 5) & 3) << 5) | (((t >> 2) & 7) << 7) | (((t >> 7) & 3) << 10);
#pragma unroll
        for (int j = 0; j < 8; j++) { int l = l0 | (j << 2); vr[j] = sr[SW(l)]; vi[j] = si[SW(l)]; }
        gbit0(vr, vi, ce[2], se[2]); gbit1(vr, vi, ce[3], se[3]); gbit2(vr, vi, ce[4], se[4]);
#pragma unroll
        for (int j = 0; j < 8; j++) { int l = l0 | (j << 2); sr[SW(l)] = vr[j]; si[SW(l)] = vi[j]; }
    }
    __syncthreads();
    {   // end q5,6,7
        int l0 = (t & 31) | (((t >> 5) & 15) << 8);
#pragma unroll
        for (int j = 0; j < 8; j++) { int l = l0 | (j << 5); vr[j] = sr[SW(l)]; vi[j] = si[SW(l)]; }
        gbit0(vr, vi, ce[5], se[5]); gbit1(vr, vi, ce[6], se[6]); gbit2(vr, vi, ce[7], se[7]);
#pragma unroll
        for (int j = 0; j < 8; j++) { int l = l0 | (j << 5); sr[SW(l)] = vr[j]; si[SW(l)] = vi[j]; }
    }
    __syncthreads();
    {   // end q12,13,14 + coalesced global store
        int l0 = (t & 255) | (((t >> 8) & 1) << 11);
#pragma unroll
        for (int j = 0; j < 8; j++) { int l = l0 | (j << 8); vr[j] = sr[SW(l)]; vi[j] = si[SW(l)]; }
        gbit0(vr, vi, ce[12], se[12]); gbit1(vr, vi, ce[13], se[13]); gbit2(vr, vi, ce[14], se[14]);
        float* wr = g_sr + (r << 16);
        float* wi = g_si + (r << 16);
#pragma unroll
        for (int j = 0; j < 8; j++) {
            int l = l0 | (j << 8);
            int b = (l & 255) | (m << 8) | ((l >> 8) << 12);
            wr[b] = vr[j]; wi[b] = vi[j];
        }
    }
}

// ---------------- K3: end RY 8..11 + probs + Z reduction ----------------
// chunk = contiguous low-12 bits; CTA = (row, hi bits 12..15)
__global__ __launch_bounds__(512) void qk3() {
    __shared__ float sr[4096], si[4096];
    __shared__ float ce4[4], se4[4];
    __shared__ float blk16[13];
    int blk = blockIdx.x, t = threadIdx.x;
    int r = blk >> 4, hi = blk & 15;
    if (t < 4) { ce4[t] = g_ce[8 + t]; se4[t] = g_se[8 + t]; }
    if (t < 13) blk16[t] = 0.f;
    __syncthreads();
    float vr[8], vi[8];
    const float* gr = g_sr + (r << 16) + (hi << 12);
    const float* gi = g_si + (r << 16) + (hi << 12);
    {   // global load + end gates q8,9,10 (local bits 8,9,10)
        int l0 = (t & 255) | (((t >> 8) & 1) << 11);
#pragma unroll
        for (int j = 0; j < 8; j++) { int l = l0 | (j << 8); vr[j] = gr[l]; vi[j] = gi[l]; }
        gbit0(vr, vi, ce4[0], se4[0]); gbit1(vr, vi, ce4[1], se4[1]); gbit2(vr, vi, ce4[2], se4[2]);
#pragma unroll
        for (int j = 0; j < 8; j++) { int l = l0 | (j << 8); sr[SW(l)] = vr[j]; si[SW(l)] = vi[j]; }
    }
    __syncthreads();
    float acc[12], tot = 0.f;
#pragma unroll
    for (int k = 0; k < 12; k++) acc[k] = 0.f;
    {   // end gate q11 (local bit 11 = j bit 2) + probability accumulation (no store)
        int l0 = (t & 511) << 2;
#pragma unroll
        for (int j = 0; j < 8; j++) {
            int l = l0 | (j & 3) | ((j >> 2) << 11);
            vr[j] = sr[SW(l)]; vi[j] = si[SW(l)];
        }
        gbit2(vr, vi, ce4[3], se4[3]);
#pragma unroll
        for (int j = 0; j < 8; j++) {
            int l = l0 | (j & 3) | ((j >> 2) << 11);
            float pr = vr[j] * vr[j] + vi[j] * vi[j];
            tot += pr;
#pragma unroll
            for (int q = 0; q < 12; q++) acc[q] += ((l >> q) & 1) ? -pr : pr;
        }
    }
    // warp shuffle reduce of 13 values
#pragma unroll
    for (int o = 16; o > 0; o >>= 1) {
        tot += __shfl_down_sync(0xffffffffu, tot, o);
#pragma unroll
        for (int k = 0; k < 12; k++) acc[k] += __shfl_down_sync(0xffffffffu, acc[k], o);
    }
    if ((t & 31) == 0) {
#pragma unroll
        for (int k = 0; k < 12; k++) atomicAdd(&blk16[k], acc[k]);
        atomicAdd(&blk16[12], tot);
    }
    __syncthreads();
    if (t < 16) {
        float v = (t < 12) ? blk16[t]
                           : blk16[12] * (((hi >> (t - 12)) & 1) ? -1.f : 1.f);
        atomicAdd(&g_z[r][t], v);
    }
}

// ---------------- K4: clip + scatter to output layout ----------------
__global__ void qk4(float* __restrict__ out) {
    int idx = blockIdx.x * blockDim.x + threadIdx.x;
    if (idx < 1024) {
        int b = idx >> 7, o = idx & 127;
        int h = o >> 5, p = (o >> 2) & 7, w = o & 3;
        float v = g_z[b * 8 + p][(h << 2) | w];
        out[idx] = fminf(1.f, fmaxf(-1.f, v));
    }
}

extern "C" void kernel_launch(void* const* d_in, const int* in_sizes, int n_in,
                              void* d_out, int out_size) {
    const float* x    = (const float*)d_in[0];
    const float* wcrz = (const float*)d_in[1];
    const float* wry  = (const float*)d_in[2];
    const float* sc   = (const float*)d_in[3];
    (void)in_sizes; (void)n_in; (void)out_size;
    qk0<<<65, 256>>>(x, wcrz, wry, sc);
    qk1<<<1024, 512>>>();
    qk2<<<1024, 512>>>();
    qk3<<<1024, 512>>>();
    qk4<<<4, 256>>>((float*)d_out);
}

// round 5
// speedup vs baseline: 1.6673x; 1.6673x over previous
#include <cuda_runtime.h>

#define N_ROWS 64
#define SD 65536
#define PI_F 3.14159265358979323846f
#define RS2 0.70710678118654752440f

// ---------------- device scratch (no allocations allowed) ----------------
static __device__ float2 g_s[N_ROWS * SD];    // 32 MB packed state (re,im)
static __device__ float  g_Pl[N_ROWS][256];   // product-state factor, qubits 0..7
static __device__ float  g_Ph[N_ROWS][256];   // product-state factor, qubits 8..15
static __device__ float2 g_A1[512];           // D1 phase, qubits 0..7   (bits 0..8)
static __device__ float2 g_B1[512];           // D1 phase, qubits 8..15  (bits 8..15, bit0)
static __device__ float2 g_C2[1024];          // D2 phase, qubits 0..7   (bits 0..9)
static __device__ float2 g_E2[1024];          // D2 phase, qubits 8..15  (bits 8..15, bits0..1)
static __device__ float  g_cm[N_ROWS][16];    // cos of merged mid RY angle /2
static __device__ float  g_sm[N_ROWS][16];
static __device__ float  g_ce[16];            // cos of end RY angle /2 (row independent)
static __device__ float  g_se[16];
static __device__ float  g_z[N_ROWS][16];     // Z expectation accumulators

// float2 smem swizzle: XOR low 4 bits with bits 4..7 -> conflict-free for all rounds
#define SW2(l) ((l) ^ (((l) >> 4) & 15))

__device__ __forceinline__ float2 cmul(float2 a, float2 b) {
    return make_float2(a.x * b.x - a.y * b.y, a.x * b.y + a.y * b.x);
}
__device__ __forceinline__ void rot2(float& a, float& b, float c, float s) {
    float t0 = a, t1 = b;
    a = c * t0 - s * t1;
    b = s * t0 + c * t1;
}
// RY gate on nibble-bit K of 16 register-resident amplitudes
template <int K>
__device__ __forceinline__ void gq(float* vr, float* vi, float c, float s) {
#pragma unroll
    for (int b = 0; b < 16; b++)
        if ((b & (1 << K)) == 0) {
            rot2(vr[b], vr[b + (1 << K)], c, s);
            rot2(vi[b], vi[b + (1 << K)], c, s);
        }
}

// ---------------- K0: build all tables + zero accumulators ----------------
__global__ void qk0(const float* __restrict__ x, const float* __restrict__ wcrz,
                    const float* __restrict__ wry, const float* __restrict__ scal) {
    __shared__ float u0[16], u1[16];
    __shared__ float cc[2][16], ss[2][16];
    int blk = blockIdx.x, tid = threadIdx.x;
    if (blk < N_ROWS) {
        int r = blk;
        if (tid < 16) {
            int q = tid, h = q >> 2, w = q & 3, b = r >> 3, p = r & 7;
            float e = tanhf(x[b * 128 + h * 32 + p * 4 + w] * scal[0]) * PI_F;
            float c, s; sincosf(0.5f * e, &s, &c);
            u0[q] = (c - s) * RS2;
            u1[q] = (c + s) * RS2;
            float mth = wry[q] + e;     // merged RY: layer0 w_ry + layer1 re-encode
            float cm, sm; sincosf(0.5f * mth, &sm, &cm);
            g_cm[r][q] = cm; g_sm[r][q] = sm;
            g_z[r][q] = 0.f;
        }
        __syncthreads();
        for (int m2 = tid; m2 < 256; m2 += blockDim.x) {
            float pl = 1.f, ph = 1.f;
#pragma unroll
            for (int q = 0; q < 8; q++) {
                pl *= ((m2 >> q) & 1) ? u1[q] : u0[q];
                ph *= ((m2 >> q) & 1) ? u1[8 + q] : u0[8 + q];
            }
            g_Pl[r][m2] = pl; g_Ph[r][m2] = ph;
        }
    } else {
        if (tid < 32) {
            int L = tid >> 4, q = tid & 15;
            float c, s; sincosf(0.5f * wcrz[L * 16 + q], &s, &c);
            cc[L][q] = c; ss[L][q] = s;
        }
        if (tid < 16) {
            float c, s; sincosf(0.5f * wry[16 + tid], &s, &c);
            g_ce[tid] = c; g_se[tid] = s;
        }
        __syncthreads();
        for (int idx = tid; idx < 512; idx += blockDim.x) {
            float2 a = make_float2(1.f, 0.f);
#pragma unroll
            for (int q = 0; q < 8; q++) {
                if ((idx >> q) & 1) {
                    float t = ((idx >> (q + 1)) & 1) ? ss[0][q] : -ss[0][q];
                    a = cmul(a, make_float2(cc[0][q], t));
                }
            }
            g_A1[idx] = a;
            float2 bp = make_float2(1.f, 0.f);
#pragma unroll
            for (int q = 8; q < 16; q++) {
                if ((idx >> (q - 8)) & 1) {
                    int bt = (q < 15) ? ((idx >> (q - 7)) & 1) : ((idx >> 8) & 1);
                    float t = bt ? ss[0][q] : -ss[0][q];
                    bp = cmul(bp, make_float2(cc[0][q], t));
                }
            }
            g_B1[idx] = bp;
        }
        for (int idx = tid; idx < 1024; idx += blockDim.x) {
            float2 a = make_float2(1.f, 0.f);
#pragma unroll
            for (int q = 0; q < 8; q++) {
                if ((idx >> q) & 1) {
                    float t = ((idx >> (q + 2)) & 1) ? ss[1][q] : -ss[1][q];
                    a = cmul(a, make_float2(cc[1][q], t));
                }
            }
            g_C2[idx] = a;
            float2 e = make_float2(1.f, 0.f);
#pragma unroll
            for (int q = 8; q < 16; q++) {
                if ((idx >> (q - 8)) & 1) {
                    int bt = (q < 14) ? ((idx >> (q - 6)) & 1)
                                      : ((q == 14) ? ((idx >> 8) & 1) : ((idx >> 9) & 1));
                    float t = bt ? ss[1][q] : -ss[1][q];
                    e = cmul(e, make_float2(cc[1][q], t));
                }
            }
            g_E2[idx] = e;
        }
    }
}

// ---------------- K1: init (P·D1) + mid RY on qubits 0..11 ----------------
// chunk = contiguous low-12 bits; CTA = (row, hi = bits 12..15); 16 amps/thread
__global__ __launch_bounds__(256) void qk1() {
    __shared__ float2 s[4096];
    __shared__ float  sPl[256], sPh[256];
    __shared__ float2 sA1[512], sB1[512];
    __shared__ float  mc[12], ms[12];
    int blk = blockIdx.x, t = threadIdx.x;
    int r = blk >> 4, hi = blk & 15;
    sPl[t] = g_Pl[r][t]; sPh[t] = g_Ph[r][t];
    sA1[t] = g_A1[t]; sA1[t + 256] = g_A1[t + 256];
    sB1[t] = g_B1[t]; sB1[t + 256] = g_B1[t + 256];
    if (t < 12) { mc[t] = g_cm[r][t]; ms[t] = g_sm[r][t]; }
    __syncthreads();
    float vr[16], vi[16];
    {   // R1: init (tables), j -> local bits 8..11, mid gates 8..11
        float  pl  = sPl[t];           // Pl idx = b&255 = t  (per-thread constant)
        float2 a1e = sA1[t];           // A1 idx = t | ((j&1)<<8)
        float2 a1o = sA1[t | 256];
        int    tb  = (t & 1) << 8;
#pragma unroll
        for (int j = 0; j < 16; j++) {
            float  p  = pl * sPh[j | (hi << 4)];                 // broadcast
            float2 a  = (j & 1) ? a1o : a1e;
            float2 bb = sB1[(j | (hi << 4)) | tb];               // near-broadcast
            vr[j] = p * (a.x * bb.x - a.y * bb.y);
            vi[j] = p * (a.x * bb.y + a.y * bb.x);
        }
        gq<0>(vr, vi, mc[8], ms[8]);  gq<1>(vr, vi, mc[9], ms[9]);
        gq<2>(vr, vi, mc[10], ms[10]); gq<3>(vr, vi, mc[11], ms[11]);
#pragma unroll
        for (int j = 0; j < 16; j++) s[SW2(t | (j << 8))] = make_float2(vr[j], vi[j]);
    }
    __syncthreads();
    {   // R2: j -> local bits 0..3, mid gates 0..3
#pragma unroll
        for (int j = 0; j < 16; j++) { float2 f = s[SW2(j | (t << 4))]; vr[j] = f.x; vi[j] = f.y; }
        gq<0>(vr, vi, mc[0], ms[0]); gq<1>(vr, vi, mc[1], ms[1]);
        gq<2>(vr, vi, mc[2], ms[2]); gq<3>(vr, vi, mc[3], ms[3]);
#pragma unroll
        for (int j = 0; j < 16; j++) s[SW2(j | (t << 4))] = make_float2(vr[j], vi[j]);
    }
    __syncthreads();
    {   // R3: j -> local bits 4..7, mid gates 4..7, global store
        int l0 = (t & 15) | ((t >> 4) << 8);
#pragma unroll
        for (int j = 0; j < 16; j++) { float2 f = s[SW2(l0 | (j << 4))]; vr[j] = f.x; vi[j] = f.y; }
        gq<0>(vr, vi, mc[4], ms[4]); gq<1>(vr, vi, mc[5], ms[5]);
        gq<2>(vr, vi, mc[6], ms[6]); gq<3>(vr, vi, mc[7], ms[7]);
        float2* g = g_s + (r << 16) + (hi << 12);
#pragma unroll
        for (int j = 0; j < 16; j++) g[l0 | (j << 4)] = make_float2(vr[j], vi[j]);
    }
}

// ---------------- K2: mid 12..15 + D2 + end 0..7,12..15 ----------------
// chunk: local bits 0..7 = global 0..7; local bits 8..11 = global 12..15
// CTA = (row, m = global bits 8..11)
__global__ __launch_bounds__(256) void qk2() {
    __shared__ float2 s[4096];
    __shared__ float  mc4[4], ms4[4], ce[16], se[16];
    int blk = blockIdx.x, t = threadIdx.x;
    int r = blk >> 4, m = blk & 15;
    if (t < 4)  { mc4[t] = g_cm[r][12 + t]; ms4[t] = g_sm[r][12 + t]; }
    if (t >= 32 && t < 48) { ce[t - 32] = g_ce[t - 32]; se[t - 32] = g_se[t - 32]; }
    __syncthreads();
    float vr[16], vi[16];
    float2* g = g_s + (r << 16);
    {   // R1: global load (j -> global bits 12..15), mid 12..15, D2, end 12..15
#pragma unroll
        for (int j = 0; j < 16; j++) {
            float2 f = g[t | (m << 8) | (j << 12)];
            vr[j] = f.x; vi[j] = f.y;
        }
        gq<0>(vr, vi, mc4[0], ms4[0]); gq<1>(vr, vi, mc4[1], ms4[1]);
        gq<2>(vr, vi, mc4[2], ms4[2]); gq<3>(vr, vi, mc4[3], ms4[3]);
        float2 c2 = g_C2[t | ((m & 3) << 8)];   // per-thread constant
        int eb = (t & 3) << 8;
#pragma unroll
        for (int j = 0; j < 16; j++) {
            float2 e2 = g_E2[(m | (j << 4)) | eb];
            float phr = c2.x * e2.x - c2.y * e2.y;
            float phi = c2.x * e2.y + c2.y * e2.x;
            float nr = vr[j] * phr - vi[j] * phi;
            vi[j] = vr[j] * phi + vi[j] * phr;
            vr[j] = nr;
        }
        gq<0>(vr, vi, ce[12], se[12]); gq<1>(vr, vi, ce[13], se[13]);
        gq<2>(vr, vi, ce[14], se[14]); gq<3>(vr, vi, ce[15], se[15]);
#pragma unroll
        for (int j = 0; j < 16; j++) s[SW2(t | (j << 8))] = make_float2(vr[j], vi[j]);
    }
    __syncthreads();
    {   // R2: j -> local bits 0..3, end 0..3
#pragma unroll
        for (int j = 0; j < 16; j++) { float2 f = s[SW2(j | (t << 4))]; vr[j] = f.x; vi[j] = f.y; }
        gq<0>(vr, vi, ce[0], se[0]); gq<1>(vr, vi, ce[1], se[1]);
        gq<2>(vr, vi, ce[2], se[2]); gq<3>(vr, vi, ce[3], se[3]);
#pragma unroll
        for (int j = 0; j < 16; j++) s[SW2(j | (t << 4))] = make_float2(vr[j], vi[j]);
    }
    __syncthreads();
    {   // R3: j -> local bits 4..7, end 4..7, global store
        int l0 = (t & 15) | ((t >> 4) << 8);
#pragma unroll
        for (int j = 0; j < 16; j++) { float2 f = s[SW2(l0 | (j << 4))]; vr[j] = f.x; vi[j] = f.y; }
        gq<0>(vr, vi, ce[4], se[4]); gq<1>(vr, vi, ce[5], se[5]);
        gq<2>(vr, vi, ce[6], se[6]); gq<3>(vr, vi, ce[7], se[7]);
#pragma unroll
        for (int j = 0; j < 16; j++) {
            int l = l0 | (j << 4);
            g[(l & 255) | (m << 8) | ((l >> 8) << 12)] = make_float2(vr[j], vi[j]);
        }
    }
}

// ---------------- K3: end 8..11 + probs + Z reduction (NO smem state) ----------------
// chunk = contiguous low-12 bits; CTA = (row, hi); j -> local bits 8..11
__global__ __launch_bounds__(256) void qk3() {
    __shared__ float ce4[4], se4[4];
    __shared__ float W[8][10];   // per-warp: tot, S0..S4, p8..p11
    int blk = blockIdx.x, t = threadIdx.x;
    int r = blk >> 4, hi = blk & 15;
    if (t < 4) { ce4[t] = g_ce[8 + t]; se4[t] = g_se[8 + t]; }
    __syncthreads();
    float vr[16], vi[16];
    const float2* g = g_s + (r << 16) + (hi << 12);
#pragma unroll
    for (int j = 0; j < 16; j++) {
        float2 f = g[t | (j << 8)];
        vr[j] = f.x; vi[j] = f.y;
    }
    gq<0>(vr, vi, ce4[0], se4[0]); gq<1>(vr, vi, ce4[1], se4[1]);
    gq<2>(vr, vi, ce4[2], se4[2]); gq<3>(vr, vi, ce4[3], se4[3]);
    float tot = 0.f, p8 = 0.f, p9 = 0.f, p10 = 0.f, p11 = 0.f;
#pragma unroll
    for (int j = 0; j < 16; j++) {
        float pr = vr[j] * vr[j] + vi[j] * vi[j];
        tot += pr;
        if (j & 1) p8  += pr;
        if (j & 2) p9  += pr;
        if (j & 4) p10 += pr;
        if (j & 8) p11 += pr;
    }
    // signed copies for lane bits 0..4 of t (sign applied pre-reduction)
    float s0 = (t & 1)  ? -tot : tot;
    float s1 = (t & 2)  ? -tot : tot;
    float s2 = (t & 4)  ? -tot : tot;
    float s3 = (t & 8)  ? -tot : tot;
    float s4 = (t & 16) ? -tot : tot;
#pragma unroll
    for (int o = 16; o > 0; o >>= 1) {
        tot += __shfl_down_sync(0xffffffffu, tot, o);
        s0  += __shfl_down_sync(0xffffffffu, s0, o);
        s1  += __shfl_down_sync(0xffffffffu, s1, o);
        s2  += __shfl_down_sync(0xffffffffu, s2, o);
        s3  += __shfl_down_sync(0xffffffffu, s3, o);
        s4  += __shfl_down_sync(0xffffffffu, s4, o);
        p8  += __shfl_down_sync(0xffffffffu, p8, o);
        p9  += __shfl_down_sync(0xffffffffu, p9, o);
        p10 += __shfl_down_sync(0xffffffffu, p10, o);
        p11 += __shfl_down_sync(0xffffffffu, p11, o);
    }
    int w = t >> 5;
    if ((t & 31) == 0) {
        W[w][0] = tot; W[w][1] = s0; W[w][2] = s1; W[w][3] = s2; W[w][4] = s3; W[w][5] = s4;
        W[w][6] = p8;  W[w][7] = p9; W[w][8] = p10; W[w][9] = p11;
    }
    __syncthreads();
    if (t < 16) {
        float z = 0.f;
#pragma unroll
        for (int k = 0; k < 8; k++) {
            if (t < 5)       z += W[k][1 + t];                                   // lane bits 0..4
            else if (t < 8)  z += (((k >> (t - 5)) & 1) ? -W[k][0] : W[k][0]);   // warp bits 5..7
            else if (t < 12) z += W[k][0] - 2.f * W[k][6 + (t - 8)];             // j bits 8..11
            else             z += W[k][0];                                       // hi bits 12..15
        }
        if (t >= 12) z = (((hi >> (t - 12)) & 1) ? -z : z);
        atomicAdd(&g_z[r][t], z);
    }
}

// ---------------- K4: clip + scatter to output layout ----------------
__global__ void qk4(float* __restrict__ out) {
    int idx = blockIdx.x * blockDim.x + threadIdx.x;
    if (idx < 1024) {
        int b = idx >> 7, o = idx & 127;
        int h = o >> 5, p = (o >> 2) & 7, w = o & 3;
        float v = g_z[b * 8 + p][(h << 2) | w];
        out[idx] = fminf(1.f, fmaxf(-1.f, v));
    }
}

extern "C" void kernel_launch(void* const* d_in, const int* in_sizes, int n_in,
                              void* d_out, int out_size) {
    const float* x    = (const float*)d_in[0];
    const float* wcrz = (const float*)d_in[1];
    const float* wry  = (const float*)d_in[2];
    const float* sc   = (const float*)d_in[3];
    (void)in_sizes; (void)n_in; (void)out_size;
    qk0<<<65, 256>>>(x, wcrz, wry, sc);
    qk1<<<1024, 256>>>();
    qk2<<<1024, 256>>>();
    qk3<<<1024, 256>>>();
    qk4<<<4, 256>>>((float*)d_out);
}

// round 6
// speedup vs baseline: 11.8708x; 7.1196x over previous
#include <cuda_runtime.h>

#define PI_F 3.14159265358979323846f
#define RS2 0.70710678118654752440f

// One warp simulates the exact 7-qubit lightcone of z_q for one (row, qubit).
// CTA = 128 threads = 4 warps = 4 qubits of one row. Grid = 64 rows * 4 = 256.
__global__ __launch_bounds__(128) void qmain(
        const float* __restrict__ x, const float* __restrict__ wcrz,
        const float* __restrict__ wry, const float* __restrict__ scal,
        float* __restrict__ out) {
    __shared__ float u0[16], u1[16];   // init amplitudes RY(enc)*H|0>
    __shared__ float cm[16], sm[16];   // merged mid RY (wry0+enc)/2 cos/sin
    __shared__ float h1[16], h2[16];   // CRZ half-angles, layer 0 / layer 1
    __shared__ float ce[16], se[16];   // end RY (wry1)/2 cos/sin

    int c = blockIdx.x;
    int r = c >> 2;                    // row 0..63
    int t = threadIdx.x;
    int lane = t & 31, w = t >> 5;
    int q = ((c & 3) << 2) | w;        // this warp's qubit 0..15

    if (t < 16) {
        int qq = t, bb = r >> 3, p = r & 7;
        float e = tanhf(x[bb * 128 + (qq >> 2) * 32 + p * 4 + (qq & 3)] * scal[0]) * PI_F;
        float cc, ss;
        sincosf(0.5f * e, &ss, &cc);
        u0[qq] = (cc - ss) * RS2;
        u1[qq] = (cc + ss) * RS2;
        sincosf(0.5f * (wry[qq] + e), &ss, &cc);   // layer0 RY merged with layer1 re-encode
        cm[qq] = cc; sm[qq] = ss;
        h1[qq] = 0.5f * wcrz[qq];
        h2[qq] = 0.5f * wcrz[16 + qq];
        sincosf(0.5f * wry[16 + qq], &ss, &cc);
        ce[qq] = cc; se[qq] = ss;
    }
    __syncthreads();

    // window qubits p0..p6 = q-3..q+3 (mod 16); local bit k <-> global qubit pk
    int p0 = (q + 13) & 15, p1 = (q + 14) & 15, p2 = (q + 15) & 15;
    int p4 = (q + 1) & 15,  p5 = (q + 2) & 15,  p6 = (q + 3) & 15;
    int b0 = lane & 1, b1 = (lane >> 1) & 1, b2 = (lane >> 2) & 1;
    int b3 = (lane >> 3) & 1, b4 = (lane >> 4) & 1;

    // init product amplitude over lane bits 0..4
    float flow = (b0 ? u1[p0] : u0[p0]) * (b1 ? u1[p1] : u0[p1]) *
                 (b2 ? u1[p2] : u0[p2]) * (b3 ? u1[q]  : u0[q])  *
                 (b4 ? u1[p4] : u0[p4]);
    // D1 phase: CRZ(control=a, target=a+1), half-angle h1[p_a], a_loc = 0..5
    float phiL = (b0 ? (b1 ? h1[p0] : -h1[p0]) : 0.f)
               + (b1 ? (b2 ? h1[p1] : -h1[p1]) : 0.f)
               + (b2 ? (b3 ? h1[p2] : -h1[p2]) : 0.f)
               + (b3 ? (b4 ? h1[q]  : -h1[q])  : 0.f);

    float vr[4], vi[4];
#pragma unroll
    for (int j = 0; j < 4; j++) {                 // j = (b5, b6)
        int b5 = j & 1, b6 = j >> 1;
        float f = flow * (b5 ? u1[p5] : u0[p5]) * (b6 ? u1[p6] : u0[p6]);
        float phi = phiL
                  + (b4 ? (b5 ? h1[p4] : -h1[p4]) : 0.f)
                  + (b5 ? (b6 ? h1[p5] : -h1[p5]) : 0.f);
        float cc, ss; sincosf(phi, &ss, &cc);
        vr[j] = f * cc;
        vi[j] = f * ss;
    }

    // mid RY on local bit1 (qubit q-2): shfl_xor 2
    {
        float cc = cm[p1], sgn = b1 ? sm[p1] : -sm[p1];
#pragma unroll
        for (int j = 0; j < 4; j++) {
            float pr = __shfl_xor_sync(0xffffffffu, vr[j], 2);
            float pi = __shfl_xor_sync(0xffffffffu, vi[j], 2);
            vr[j] = cc * vr[j] + sgn * pr;
            vi[j] = cc * vi[j] + sgn * pi;
        }
    }
    // mid RY on local bit3 (qubit q): shfl_xor 8
    {
        float cc = cm[q], sgn = b3 ? sm[q] : -sm[q];
#pragma unroll
        for (int j = 0; j < 4; j++) {
            float pr = __shfl_xor_sync(0xffffffffu, vr[j], 8);
            float pi = __shfl_xor_sync(0xffffffffu, vi[j], 8);
            vr[j] = cc * vr[j] + sgn * pr;
            vi[j] = cc * vi[j] + sgn * pi;
        }
    }
    // mid RY on local bit5 (qubit q+2): register pairs (0,1) and (2,3)
    {
        float cc = cm[p5], ss = sm[p5];
#pragma unroll
        for (int jj = 0; jj < 4; jj += 2) {
            float r0 = vr[jj], r1 = vr[jj + 1];
            vr[jj] = cc * r0 - ss * r1;  vr[jj + 1] = ss * r0 + cc * r1;
            float i0 = vi[jj], i1 = vi[jj + 1];
            vi[jj] = cc * i0 - ss * i1;  vi[jj + 1] = ss * i0 + cc * i1;
        }
    }
    // D2 phases: CRZ(q-2 -> q) = (ctrl b1, tgt b3, h2[p1]); CRZ(q -> q+2) = (ctrl b3, tgt b5, h2[q])
    {
        float base = b1 ? (b3 ? h2[p1] : -h2[p1]) : 0.f;
        float ang0 = base + (b3 ? -h2[q] : 0.f);   // b5 = 0
        float ang1 = base + (b3 ?  h2[q] : 0.f);   // b5 = 1
        float c0, s0, c1, s1;
        sincosf(ang0, &s0, &c0);
        sincosf(ang1, &s1, &c1);
#pragma unroll
        for (int j = 0; j < 4; j++) {
            float cc = (j & 1) ? c1 : c0, ss = (j & 1) ? s1 : s0;
            float nr = vr[j] * cc - vi[j] * ss;
            vi[j] = vr[j] * ss + vi[j] * cc;
            vr[j] = nr;
        }
    }
    // end RY on local bit3 (qubit q): shfl_xor 8
    {
        float cc = ce[q], sgn = b3 ? se[q] : -se[q];
#pragma unroll
        for (int j = 0; j < 4; j++) {
            float pr = __shfl_xor_sync(0xffffffffu, vr[j], 8);
            float pi = __shfl_xor_sync(0xffffffffu, vi[j], 8);
            vr[j] = cc * vr[j] + sgn * pr;
            vi[j] = cc * vi[j] + sgn * pi;
        }
    }
    // z_q = sum (1 - 2*bit3) * |amp|^2, warp reduce
    float acc = 0.f;
#pragma unroll
    for (int j = 0; j < 4; j++) acc += vr[j] * vr[j] + vi[j] * vi[j];
    acc = b3 ? -acc : acc;
#pragma unroll
    for (int o = 16; o > 0; o >>= 1) acc += __shfl_down_sync(0xffffffffu, acc, o);
    if (lane == 0) {
        int bb = r >> 3, p = r & 7;
        out[bb * 128 + (q >> 2) * 32 + p * 4 + (q & 3)] = fminf(1.f, fmaxf(-1.f, acc));
    }
}

extern "C" void kernel_launch(void* const* d_in, const int* in_sizes, int n_in,
                              void* d_out, int out_size) {
    const float* x    = (const float*)d_in[0];
    const float* wcrz = (const float*)d_in[1];
    const float* wry  = (const float*)d_in[2];
    const float* sc   = (const float*)d_in[3];
    (void)in_sizes; (void)n_in; (void)out_size;
    qmain<<<256, 128>>>(x, wcrz, wry, sc, (float*)d_out);
}

// round 7
// speedup vs baseline: 11.9279x; 1.0048x over previous
#include <cuda_runtime.h>

#define PI_F 3.14159265358979323846f
#define RS2 0.70710678118654752440f

// One warp = exact 7-qubit lightcone of z_q for one (row, qubit).
// Lane bits = (b0,b1,b2,b4,b6); register index j = b3 + 2*b5.
// CTA = 4 warps (4 qubits of one row); grid = 64 rows * 4 = 256.
__global__ __launch_bounds__(128) void qmain(
        const float* __restrict__ x, const float* __restrict__ wcrz,
        const float* __restrict__ wry, const float* __restrict__ scal,
        float* __restrict__ out) {
    __shared__ float2 Wu[4][16];   // (u0, u1): init amps RY(enc)·H|0>
    __shared__ float  Wh1[4][16];  // layer-0 CRZ half-angle
    __shared__ float2 Wm[4][16];   // (cos, sin) merged mid RY (w0+enc)/2
    __shared__ float2 Wh2[4][16];  // cis(layer-1 CRZ half-angle)
    __shared__ float2 We[4][16];   // (cos, sin) end RY w1/2

    int c = blockIdx.x, r = c >> 2;
    int t = threadIdx.x, lane = t & 31, w = t >> 5;
    int q = ((c & 3) << 2) | w;

    // per-warp redundant prep (lanes 0..15), no CTA barrier
    if (lane < 16) {
        int qq = lane, bb = r >> 3, p = r & 7;
        float xv = x[bb * 128 + (qq >> 2) * 32 + p * 4 + (qq & 3)] * scal[0];
        float ex = __expf(2.f * xv);
        float e = __fdividef(ex - 1.f, ex + 1.f) * PI_F;   // pi * tanh
        float sh, ch; __sincosf(0.5f * e, &sh, &ch);
        Wu[w][qq] = make_float2((ch - sh) * RS2, (ch + sh) * RS2);
        float sm_, cm_; __sincosf(0.5f * (wry[qq] + e), &sm_, &cm_);
        Wm[w][qq] = make_float2(cm_, sm_);
        Wh1[w][qq] = 0.5f * wcrz[qq];
        float s2, c2; __sincosf(0.5f * wcrz[16 + qq], &s2, &c2);
        Wh2[w][qq] = make_float2(c2, s2);
        float se_, ce_; __sincosf(0.5f * wry[16 + qq], &se_, &ce_);
        We[w][qq] = make_float2(ce_, se_);
    }
    __syncwarp();

    // window qubits: local bit k <-> global qubit q-3+k (mod 16)
    int p0 = (q + 13) & 15, p1 = (q + 14) & 15, p2 = (q + 15) & 15;
    int p4 = (q + 1) & 15,  p5 = (q + 2) & 15,  p6 = (q + 3) & 15;
    int b0 = lane & 1, b1 = (lane >> 1) & 1, b2 = (lane >> 2) & 1;
    int b4 = (lane >> 3) & 1, b6 = (lane >> 4) & 1;

    // broadcast smem reads (same address across warp)
    float2 U0 = Wu[w][p0], U1 = Wu[w][p1], U2 = Wu[w][p2];
    float2 Uq = Wu[w][q],  U4 = Wu[w][p4], U5 = Wu[w][p5], U6 = Wu[w][p6];
    float h1p0 = Wh1[w][p0], h1p1 = Wh1[w][p1], h1p2 = Wh1[w][p2];
    float h1q = Wh1[w][q], h1p4 = Wh1[w][p4], h1p5 = Wh1[w][p5];
    float2 M1 = Wm[w][p1], Mq = Wm[w][q], M5 = Wm[w][p5];
    float2 Ha = Wh2[w][p1], Hb = Wh2[w][q];
    float2 E = We[w][q];

    // init product over lane bits
    float base = (b0 ? U0.y : U0.x) * (b1 ? U1.y : U1.x) * (b2 ? U2.y : U2.x)
               * (b4 ? U4.y : U4.x) * (b6 ? U6.y : U6.x);
    // D1 ring phase: sum of control? (target? +h : -h) : 0 over the 6 window pairs
    float phiL = (b0 ? (b1 ? h1p0 : -h1p0) : 0.f)
               + (b1 ? (b2 ? h1p1 : -h1p1) : 0.f);
    float A0 = b2 ? -h1p2 : 0.f;                               // b3 = 0
    float A1 = (b2 ? h1p2 : 0.f) + (b4 ? h1q : -h1q);          // b3 = 1
    float B0 = b4 ? -h1p4 : 0.f;                               // b5 = 0
    float B1 = (b4 ? h1p4 : 0.f) + (b6 ? h1p5 : -h1p5);        // b5 = 1

    float vr[4], vi[4];
    {
        float ang[4] = { phiL + A0 + B0, phiL + A1 + B0,
                         phiL + A0 + B1, phiL + A1 + B1 };     // j = b3 + 2*b5
        float fj[4] = { base * Uq.x * U5.x, base * Uq.y * U5.x,
                        base * Uq.x * U5.y, base * Uq.y * U5.y };
#pragma unroll
        for (int j = 0; j < 4; j++) {
            float s_, c_; __sincosf(ang[j], &s_, &c_);
            vr[j] = fj[j] * c_; vi[j] = fj[j] * s_;
        }
    }
    // mid RY on qubit q-2 (lane bit 1): the only shfl gate
    {
        float cc = M1.x, sg = b1 ? M1.y : -M1.y;
#pragma unroll
        for (int j = 0; j < 4; j++) {
            float pr = __shfl_xor_sync(0xffffffffu, vr[j], 2);
            float pi = __shfl_xor_sync(0xffffffffu, vi[j], 2);
            vr[j] = cc * vr[j] + sg * pr;
            vi[j] = cc * vi[j] + sg * pi;
        }
    }
    // mid RY on qubit q (register bit b3): pairs (0,1),(2,3)
    {
        float cc = Mq.x, ss = Mq.y;
#pragma unroll
        for (int jj = 0; jj < 4; jj += 2) {
            float r0 = vr[jj], r1 = vr[jj + 1];
            vr[jj] = cc * r0 - ss * r1;  vr[jj + 1] = ss * r0 + cc * r1;
            float i0 = vi[jj], i1 = vi[jj + 1];
            vi[jj] = cc * i0 - ss * i1;  vi[jj + 1] = ss * i0 + cc * i1;
        }
    }
    // mid RY on qubit q+2 (register bit b5): pairs (0,2),(1,3)
    {
        float cc = M5.x, ss = M5.y;
#pragma unroll
        for (int jj = 0; jj < 2; jj++) {
            float r0 = vr[jj], r1 = vr[jj + 2];
            vr[jj] = cc * r0 - ss * r1;  vr[jj + 2] = ss * r0 + cc * r1;
            float i0 = vi[jj], i1 = vi[jj + 2];
            vi[jj] = cc * i0 - ss * i1;  vi[jj + 2] = ss * i0 + cc * i1;
        }
    }
    // D2 diagonal: CRZ(q-2 -> q) uses (b1,b3); CRZ(q -> q+2) uses (b3,b5)
    {
        float pr0 = b1 ? Ha.x : 1.f, pi0 = b1 ? -Ha.y : 0.f;   // b3 = 0 factor
        float prA = pr0,             piA = b1 ?  Ha.y : 0.f;   // b3 = 1 base
        // j=0 (b3=0,b5=0) and j=2 (b3=0,b5=1): phase (pr0, pi0)
#pragma unroll
        for (int jj = 0; jj < 4; jj += 2) {
            float nr = vr[jj] * pr0 - vi[jj] * pi0;
            vi[jj] = vr[jj] * pi0 + vi[jj] * pr0;
            vr[jj] = nr;
        }
        // j=1 (b3=1,b5=0): (prA,piA)*(Hb.x,-Hb.y); j=3 (b3=1,b5=1): (prA,piA)*(Hb.x,+Hb.y)
        float pr1 = prA * Hb.x + piA * Hb.y, pi1 = -prA * Hb.y + piA * Hb.x;
        float pr3 = prA * Hb.x - piA * Hb.y, pi3 =  prA * Hb.y + piA * Hb.x;
        float nr1 = vr[1] * pr1 - vi[1] * pi1;
        vi[1] = vr[1] * pi1 + vi[1] * pr1; vr[1] = nr1;
        float nr3 = vr[3] * pr3 - vi[3] * pi3;
        vi[3] = vr[3] * pi3 + vi[3] * pr3; vr[3] = nr3;
    }
    // end RY on qubit q (register bit b3)
    {
        float cc = E.x, ss = E.y;
#pragma unroll
        for (int jj = 0; jj < 4; jj += 2) {
            float r0 = vr[jj], r1 = vr[jj + 1];
            vr[jj] = cc * r0 - ss * r1;  vr[jj + 1] = ss * r0 + cc * r1;
            float i0 = vi[jj], i1 = vi[jj + 1];
            vi[jj] = cc * i0 - ss * i1;  vi[jj + 1] = ss * i0 + cc * i1;
        }
    }
    // z_q = sum (1 - 2*b3) |amp|^2 ; b3 = j&1
    float acc = (vr[0] * vr[0] + vi[0] * vi[0]) - (vr[1] * vr[1] + vi[1] * vi[1])
              + (vr[2] * vr[2] + vi[2] * vi[2]) - (vr[3] * vr[3] + vi[3] * vi[3]);
#pragma unroll
    for (int o = 16; o > 0; o >>= 1) acc += __shfl_down_sync(0xffffffffu, acc, o);
    if (lane == 0) {
        int bb = r >> 3, p = r & 7;
        out[bb * 128 + (q >> 2) * 32 + p * 4 + (q & 3)] = fminf(1.f, fmaxf(-1.f, acc));
    }
}

extern "C" void kernel_launch(void* const* d_in, const int* in_sizes, int n_in,
                              void* d_out, int out_size) {
    const float* x    = (const float*)d_in[0];
    const float* wcrz = (const float*)d_in[1];
    const float* wry  = (const float*)d_in[2];
    const float* sc   = (const float*)d_in[3];
    (void)in_sizes; (void)n_in; (void)out_size;
    qmain<<<256, 128>>>(x, wcrz, wry, sc, (float*)d_out);
}